// round 14
// baseline (speedup 1.0000x reference)
#include <cuda_runtime.h>
#include <cuda_fp16.h>
#include <cstdint>

#define NN 50000
#define EE 800000
#define NWTOT 393216
#define BM 128
#define P32 20   /* words per SMEM row: 40 halves, 80 B pitch */

// ---------------- static device scratch (no runtime alloc allowed) ----------
__device__ float g_bufA[(size_t)NN * 512];
__device__ float g_bufB[(size_t)NN * 512];
__device__ float g_agg [(size_t)NN * 256];
__device__ int   g_deg[NN];
__device__ float g_deg_inv[NN];
__device__ int   g_row_off[NN];
__device__ int   g_fill[NN];
__device__ int   g_csr_src[EE];
__device__ int   g_counter;
__device__ __half g_Whi[NWTOT];
__device__ __half g_Wlo[NWTOT];

// ---------------- graph build ----------------------------------------------
__global__ void k_zero_deg() {
    int i = blockIdx.x * blockDim.x + threadIdx.x;
    if (i < NN) g_deg[i] = 0;
    if (i == 0) g_counter = 0;
}

__global__ void k_count_deg(const int* __restrict__ dst) {
    int e = blockIdx.x * blockDim.x + threadIdx.x;
    if (e < EE) atomicAdd(&g_deg[dst[e]], 1);
}

__global__ void k_offsets() {
    __shared__ int sh[256];
    __shared__ int base;
    int t = threadIdx.x;
    int i = blockIdx.x * 256 + t;
    int d = (i < NN) ? g_deg[i] : 0;
    sh[t] = d;
    __syncthreads();
    #pragma unroll
    for (int off = 1; off < 256; off <<= 1) {
        int v = (t >= off) ? sh[t - off] : 0;
        __syncthreads();
        sh[t] += v;
        __syncthreads();
    }
    int incl = sh[t];
    if (t == 255) base = atomicAdd(&g_counter, incl);
    __syncthreads();
    if (i < NN) {
        int o = base + incl - d;
        g_row_off[i] = o;
        g_fill[i]    = o;
        g_deg_inv[i] = 1.0f / fmaxf((float)d, 1.0f);
    }
}

__global__ void k_fill_csr(const int* __restrict__ src, const int* __restrict__ dst) {
    int e = blockIdx.x * blockDim.x + threadIdx.x;
    if (e < EE) {
        int p = atomicAdd(&g_fill[dst[e]], 1);
        g_csr_src[p] = src[e];
    }
}

// ---------------- weight pre-conversion to fp16 hi/lo ------------------------
struct WP { const float* w[10]; };

__global__ void k_convW(WP p) {
    const int off[11] = {0, 16384, 32768, 40960, 49152, 57344,
                         65536, 98304, 131072, 262144, 393216};
    int i = blockIdx.x * 256 + threadIdx.x;
    if (i >= NWTOT) return;
    int s = 0;
    #pragma unroll
    for (int j = 1; j < 10; j++) if (i >= off[j]) s = j;
    float v = p.w[s][i - off[s]];
    __half h = __float2half_rn(v);
    g_Whi[i] = h;
    g_Wlo[i] = __float2half_rn(v - __half2float(h));
}

// ---------------- aggregation (float4 lanes, multi-node blocks) -------------
__global__ void k_aggregate4(const float4* __restrict__ h4, float4* __restrict__ agg4,
                             int din4) {
    int n = blockIdx.x * blockDim.y + threadIdx.y;
    if (n >= NN) return;
    int k = threadIdx.x;
    int s = g_row_off[n];
    int e1 = s + g_deg[n];
    float4 acc = make_float4(0.f, 0.f, 0.f, 0.f);
    int e = s;
    for (; e + 3 < e1; e += 4) {
        int s0 = g_csr_src[e + 0];
        int s1 = g_csr_src[e + 1];
        int s2 = g_csr_src[e + 2];
        int s3 = g_csr_src[e + 3];
        float4 v0 = h4[(size_t)s0 * din4 + k];
        float4 v1 = h4[(size_t)s1 * din4 + k];
        float4 v2 = h4[(size_t)s2 * din4 + k];
        float4 v3 = h4[(size_t)s3 * din4 + k];
        acc.x += (v0.x + v1.x) + (v2.x + v3.x);
        acc.y += (v0.y + v1.y) + (v2.y + v3.y);
        acc.z += (v0.z + v1.z) + (v2.z + v3.z);
        acc.w += (v0.w + v1.w) + (v2.w + v3.w);
    }
    for (; e < e1; e++) {
        float4 v = h4[(size_t)g_csr_src[e] * din4 + k];
        acc.x += v.x; acc.y += v.y; acc.z += v.z; acc.w += v.w;
    }
    float di = g_deg_inv[n];
    acc.x *= di; acc.y *= di; acc.z *= di; acc.w *= di;
    agg4[(size_t)n * din4 + k] = acc;
}

// ---------------- fp16 mma helpers ------------------------------------------
__device__ __forceinline__ void split2p(float x, float y, uint32_t& hi2, uint32_t& lo2) {
    asm("cvt.rn.f16x2.f32 %0, %1, %2;" : "=r"(hi2) : "f"(y), "f"(x));
    float hx, hy;
    asm("{\n\t.reg .b16 l, h;\n\tmov.b32 {l, h}, %2;\n\t"
        "cvt.f32.f16 %0, l;\n\tcvt.f32.f16 %1, h;\n\t}"
        : "=f"(hx), "=f"(hy) : "r"(hi2));
    float lx = x - hx, ly = y - hy;
    asm("cvt.rn.f16x2.f32 %0, %1, %2;" : "=r"(lo2) : "f"(ly), "f"(lx));
}

__device__ __forceinline__ void mma_f16(float* c, const uint32_t* a, const uint32_t* b) {
    asm volatile(
        "mma.sync.aligned.m16n8k16.row.col.f32.f16.f16.f32 "
        "{%0,%1,%2,%3}, {%4,%5,%6,%7}, {%8,%9}, {%0,%1,%2,%3};"
        : "+f"(c[0]), "+f"(c[1]), "+f"(c[2]), "+f"(c[3])
        : "r"(a[0]), "r"(a[1]), "r"(a[2]), "r"(a[3]), "r"(b[0]), "r"(b[1]));
}

__device__ __forceinline__ void ldm_x4(uint32_t* r, uint32_t addr) {
    asm volatile("ldmatrix.sync.aligned.m8n8.x4.shared.b16 {%0,%1,%2,%3}, [%4];"
                 : "=r"(r[0]), "=r"(r[1]), "=r"(r[2]), "=r"(r[3]) : "r"(addr));
}
__device__ __forceinline__ void ldm_x2(uint32_t* r, uint32_t addr) {
    asm volatile("ldmatrix.sync.aligned.m8n8.x2.shared.b16 {%0,%1}, [%2];"
                 : "=r"(r[0]), "=r"(r[1]) : "r"(addr));
}

// ---------------- gemm core: C = [relu](A @ W^T [+ Cadd] [+ bias]) ----------
template<int BN>
__device__ __forceinline__ void gemm_core(
    const float* __restrict__ A,
    const __half* __restrict__ Bh_, const __half* __restrict__ Bl_,
    const float* __restrict__ Cadd, const float* __restrict__ bias,
    float* __restrict__ C, int din, int dout, int bid, bool doRelu)
{
    constexpr int WN = BN / 4;
    constexpr int NT = WN / 8;
    constexpr int A_IT = 4;
    constexpr int B_IT = BN / 64;

    __shared__ uint32_t AsH[BM * P32], AsL[BM * P32];
    __shared__ uint32_t BsH[BN * P32], BsL[BN * P32];

    int tid = threadIdx.x;
    int wid = tid >> 5, lane = tid & 31;
    int wm = wid >> 2, wn = wid & 3;
    int lr = lane >> 2, q = lane & 3;
    const int nRowT = (NN + BM - 1) / BM;
    int rowBase = (bid % nRowT) * BM;
    int colBase = (bid / nRowT) * BN;

    int aRow = (lane & 7) + 8 * ((lane >> 3) & 1);
    int aCol = 16 * ((lane >> 4) & 1);
    int bRow = lane & 7;
    int bCol = 16 * ((lane >> 3) & 1);
    uint32_t aBaseH = (uint32_t)__cvta_generic_to_shared(AsH) + (wm * 64 + aRow) * 80 + aCol;
    uint32_t aBaseL = (uint32_t)__cvta_generic_to_shared(AsL) + (wm * 64 + aRow) * 80 + aCol;
    uint32_t bBaseH = (uint32_t)__cvta_generic_to_shared(BsH) + (wn * WN + bRow) * 80 + bCol;
    uint32_t bBaseL = (uint32_t)__cvta_generic_to_shared(BsL) + (wn * WN + bRow) * 80 + bCol;

    float acc[4][NT][4];
    #pragma unroll
    for (int i = 0; i < 4; i++)
        #pragma unroll
        for (int j = 0; j < NT; j++)
            #pragma unroll
            for (int p = 0; p < 4; p++) acc[i][j][p] = 0.0f;

    const int nCh = din >> 5;
    float4 pa[A_IT];
    uint4 pbh[B_IT], pbl[B_IT];

    auto loadChunk = [&](int ch) {
        int kk = ch << 5;
        #pragma unroll
        for (int it = 0; it < A_IT; it++) {
            int i = tid + it * 256;
            int r = i >> 3, c4 = (i & 7) << 2;
            int gr = rowBase + r;
            pa[it] = (gr < NN) ? *reinterpret_cast<const float4*>(&A[(size_t)gr * din + kk + c4])
                               : make_float4(0.f, 0.f, 0.f, 0.f);
        }
        #pragma unroll
        for (int it = 0; it < B_IT; it++) {
            int i = tid + it * 256;
            int r = i >> 2, c8 = (i & 3) << 3;
            size_t goff = (size_t)(colBase + r) * din + kk + c8;
            pbh[it] = *reinterpret_cast<const uint4*>(&Bh_[goff]);
            pbl[it] = *reinterpret_cast<const uint4*>(&Bl_[goff]);
        }
    };

    loadChunk(0);

    for (int ch = 0; ch < nCh; ch++) {
        #pragma unroll
        for (int it = 0; it < A_IT; it++) {
            int i = tid + it * 256;
            int r = i >> 3, w = (i & 7) << 1;
            uint32_t h0, l0, h1, l1;
            split2p(pa[it].x, pa[it].y, h0, l0);
            split2p(pa[it].z, pa[it].w, h1, l1);
            AsH[r * P32 + w] = h0; AsH[r * P32 + w + 1] = h1;
            AsL[r * P32 + w] = l0; AsL[r * P32 + w + 1] = l1;
        }
        #pragma unroll
        for (int it = 0; it < B_IT; it++) {
            int i = tid + it * 256;
            int r = i >> 2, w4 = (i & 3) << 2;
            *reinterpret_cast<uint4*>(&BsH[r * P32 + w4]) = pbh[it];
            *reinterpret_cast<uint4*>(&BsL[r * P32 + w4]) = pbl[it];
        }
        __syncthreads();

        if (ch + 1 < nCh) loadChunk(ch + 1);

        #pragma unroll
        for (int ks = 0; ks < 2; ks++) {
            uint32_t kb = (uint32_t)(ks * 32);
            uint32_t ah[4][4], al[4][4], bh[NT][2], bl[NT][2];
            #pragma unroll
            for (int mt = 0; mt < 4; mt++) {
                uint32_t moff = (uint32_t)(mt * 16 * 80) + kb;
                ldm_x4(ah[mt], aBaseH + moff);
                ldm_x4(al[mt], aBaseL + moff);
            }
            #pragma unroll
            for (int nt = 0; nt < NT; nt++) {
                uint32_t noff = (uint32_t)(nt * 8 * 80) + kb;
                ldm_x2(bh[nt], bBaseH + noff);
                ldm_x2(bl[nt], bBaseL + noff);
            }
            #pragma unroll
            for (int mt = 0; mt < 4; mt++)
                #pragma unroll
                for (int nt = 0; nt < NT; nt++)
                    mma_f16(acc[mt][nt], ah[mt], bh[nt]);
            #pragma unroll
            for (int mt = 0; mt < 4; mt++)
                #pragma unroll
                for (int nt = 0; nt < NT; nt++)
                    mma_f16(acc[mt][nt], al[mt], bh[nt]);
            #pragma unroll
            for (int mt = 0; mt < 4; mt++)
                #pragma unroll
                for (int nt = 0; nt < NT; nt++)
                    mma_f16(acc[mt][nt], ah[mt], bl[nt]);
        }
        __syncthreads();
    }

    #pragma unroll
    for (int mt = 0; mt < 4; mt++) {
        int r0 = rowBase + wm * 64 + mt * 16 + lr;
        int r1 = r0 + 8;
        #pragma unroll
        for (int nt = 0; nt < NT; nt++) {
            int c = colBase + wn * WN + nt * 8 + q * 2;
            float b0 = 0.f, b1 = 0.f;
            if (bias) { b0 = bias[c]; b1 = bias[c + 1]; }
            if (r0 < NN) {
                float v0 = acc[mt][nt][0] + b0;
                float v1 = acc[mt][nt][1] + b1;
                if (Cadd) {
                    float2 pz = *reinterpret_cast<const float2*>(&Cadd[(size_t)r0 * dout + c]);
                    v0 += pz.x; v1 += pz.y;
                }
                if (doRelu) { v0 = fmaxf(v0, 0.f); v1 = fmaxf(v1, 0.f); }
                float2 v; v.x = v0; v.y = v1;
                *reinterpret_cast<float2*>(&C[(size_t)r0 * dout + c]) = v;
            }
            if (r1 < NN) {
                float v0 = acc[mt][nt][2] + b0;
                float v1 = acc[mt][nt][3] + b1;
                if (Cadd) {
                    float2 pz = *reinterpret_cast<const float2*>(&Cadd[(size_t)r1 * dout + c]);
                    v0 += pz.x; v1 += pz.y;
                }
                if (doRelu) { v0 = fmaxf(v0, 0.f); v1 = fmaxf(v1, 0.f); }
                float2 v; v.x = v0; v.y = v1;
                *reinterpret_cast<float2*>(&C[(size_t)r1 * dout + c]) = v;
            }
        }
    }
}

// Cpart = h @ Wr^T
template<int BN>
__global__ __launch_bounds__(256)
void k_gemmR(const float* __restrict__ h,
             const __half* __restrict__ WhR, const __half* __restrict__ WlR,
             float* __restrict__ Cpart, int din, int dout)
{
    gemm_core<BN>(h, WhR, WlR, nullptr, nullptr, Cpart, din, dout, blockIdx.x, false);
}

// hnext = relu(agg @ Wl^T + Cpart + bias)   (Cpart == hnext, disjoint RMW)
template<int BN>
__global__ __launch_bounds__(256)
void k_gemm2(const float* __restrict__ agg,
             const __half* __restrict__ WhL, const __half* __restrict__ WlL,
             const float* __restrict__ Cpart, const float* __restrict__ bias,
             float* __restrict__ C, int din, int dout)
{
    gemm_core<BN>(agg, WhL, WlL, Cpart, bias, C, din, dout, blockIdx.x, true);
}

// ---------------- head: logits = h @ Wout^T + bout; softmax -----------------
__global__ void k_head(const float4* __restrict__ h4, const float4* __restrict__ Wout4,
                       const float* __restrict__ bout, float* __restrict__ out) {
    int gwarp = (blockIdx.x * blockDim.x + threadIdx.x) >> 5;
    int lane  = threadIdx.x & 31;
    if (gwarp >= NN) return;
    const float4* hr = h4 + (size_t)gwarp * 128;
    float s[4] = {0.f, 0.f, 0.f, 0.f};
    #pragma unroll
    for (int it = 0; it < 4; it++) {
        int i = lane + it * 32;
        float4 hv = hr[i];
        #pragma unroll
        for (int c = 0; c < 4; c++) {
            float4 wv = Wout4[c * 128 + i];
            s[c] += hv.x * wv.x + hv.y * wv.y + hv.z * wv.z + hv.w * wv.w;
        }
    }
    #pragma unroll
    for (int off = 16; off > 0; off >>= 1)
        #pragma unroll
        for (int c = 0; c < 4; c++)
            s[c] += __shfl_xor_sync(0xFFFFFFFF, s[c], off);
    if (lane == 0) {
        float l[4];
        float m = -1e30f;
        #pragma unroll
        for (int c = 0; c < 4; c++) { l[c] = s[c] + bout[c]; m = fmaxf(m, l[c]); }
        float den = 0.f;
        #pragma unroll
        for (int c = 0; c < 4; c++) { l[c] = __expf(l[c] - m); den += l[c]; }
        float inv = 1.0f / den;
        #pragma unroll
        for (int c = 0; c < 4; c++) out[(size_t)gwarp * 4 + c] = l[c] * inv;
    }
}

// ---------------- driver -----------------------------------------------------
extern "C" void kernel_launch(void* const* d_in, const int* in_sizes, int n_in,
                              void* d_out, int out_size)
{
    const float* x    = (const float*)d_in[0];
    const float* Wl[5] = {(const float*)d_in[1],  (const float*)d_in[4],
                          (const float*)d_in[7],  (const float*)d_in[10],
                          (const float*)d_in[13]};
    const float* bl[5] = {(const float*)d_in[2],  (const float*)d_in[5],
                          (const float*)d_in[8],  (const float*)d_in[11],
                          (const float*)d_in[14]};
    const float* Wr[5] = {(const float*)d_in[3],  (const float*)d_in[6],
                          (const float*)d_in[9],  (const float*)d_in[12],
                          (const float*)d_in[15]};
    const float* Wout = (const float*)d_in[16];
    const float* bout = (const float*)d_in[17];
    const int*   ei   = (const int*)d_in[18];
    const int* src = ei;
    const int* dst = ei + EE;

    float *bufA, *bufB, *aggp;
    __half *whi, *wlo;
    cudaGetSymbolAddress((void**)&bufA, g_bufA);
    cudaGetSymbolAddress((void**)&bufB, g_bufB);
    cudaGetSymbolAddress((void**)&aggp, g_agg);
    cudaGetSymbolAddress((void**)&whi, g_Whi);
    cudaGetSymbolAddress((void**)&wlo, g_Wlo);

    // side stream + events (non-blocking; dependencies via events only)
    cudaStream_t s2;
    cudaStreamCreateWithFlags(&s2, cudaStreamNonBlocking);
    cudaEvent_t evW, evR, evH;
    cudaEventCreateWithFlags(&evW, cudaEventDisableTiming);
    cudaEventCreateWithFlags(&evR, cudaEventDisableTiming);
    cudaEventCreateWithFlags(&evH, cudaEventDisableTiming);

    // 0. convert weights (stream 0), mark ready
    WP wp;
    for (int i = 0; i < 5; i++) { wp.w[2 * i] = Wl[i]; wp.w[2 * i + 1] = Wr[i]; }
    k_convW<<<(NWTOT + 255) / 256, 256>>>(wp);
    cudaEventRecord(evW, 0);

    // 1. build CSR by dst (stream 0)
    k_zero_deg<<<(NN + 255) / 256, 256>>>();
    k_count_deg<<<(EE + 255) / 256, 256>>>(dst);
    k_offsets<<<(NN + 255) / 256, 256>>>();
    k_fill_csr<<<(EE + 255) / 256, 256>>>(src, dst);

    // 2. layers: gemmR on s2 overlaps aggregate on stream 0
    const int dins[5]  = {128, 128, 64, 128, 256};
    const int douts[5] = {128,  64, 128, 256, 512};
    const int woff[10] = {0, 16384, 32768, 40960, 49152, 57344,
                          65536, 98304, 131072, 262144};
    const int nRowT = (NN + BM - 1) / BM;   // 391
    const float* hcur = x;
    float* bufs[2] = {bufA, bufB};
    for (int i = 0; i < 5; i++) {
        int din = dins[i], dout = douts[i];
        int din4 = din / 4;
        int npb = 128 / din4;
        float* hnext = bufs[i & 1];
        const __half* whl = whi + woff[2 * i];
        const __half* wll = wlo + woff[2 * i];
        const __half* whr = whi + woff[2 * i + 1];
        const __half* wlr = wlo + woff[2 * i + 1];

        // gemmR on side stream: needs weights (i==0) or h from previous gemm2
        cudaStreamWaitEvent(s2, (i == 0) ? evW : evH, 0);
        if (dout >= 128) {
            int nGem = nRowT * (dout / 128);
            k_gemmR<128><<<nGem, 256, 0, s2>>>(hcur, whr, wlr, hnext, din, dout);
        } else {
            k_gemmR<64><<<nRowT, 256, 0, s2>>>(hcur, whr, wlr, hnext, din, dout);
        }
        cudaEventRecord(evR, s2);

        // aggregation on stream 0 (in-order after CSR / previous gemm2)
        dim3 ablk(din4, npb);
        k_aggregate4<<<(NN + npb - 1) / npb, ablk>>>(
            (const float4*)hcur, (float4*)aggp, din4);

        // gemm2 on stream 0 waits for gemmR
        cudaStreamWaitEvent(0, evR, 0);
        if (dout >= 128) {
            int nGem = nRowT * (dout / 128);
            k_gemm2<128><<<nGem, 256>>>(aggp, whl, wll, hnext, bl[i], hnext, din, dout);
        } else {
            k_gemm2<64><<<nRowT, 256>>>(aggp, whl, wll, hnext, bl[i], hnext, din, dout);
        }
        cudaEventRecord(evH, 0);
        hcur = hnext;
    }

    // 3. head + softmax (stream 0)
    k_head<<<(NN * 32 + 255) / 256, 256>>>((const float4*)hcur, (const float4*)Wout,
                                           bout, (float*)d_out);

    // cleanup only when not capturing (destroying a capturing stream would
    // invalidate the graph); during capture we intentionally leak one set.
    cudaStreamCaptureStatus cs = cudaStreamCaptureStatusNone;
    cudaStreamIsCapturing(s2, &cs);
    if (cs == cudaStreamCaptureStatusNone) {
        cudaStreamDestroy(s2);
        cudaEventDestroy(evW);
        cudaEventDestroy(evR);
        cudaEventDestroy(evH);
    }
}

// round 15
// speedup vs baseline: 1.2837x; 1.2837x over previous
#include <cuda_runtime.h>
#include <cuda_fp16.h>
#include <cstdint>

#define NN 50000
#define EE 800000
#define NWTOT 393216
#define BM 128
#define P32 20   /* words per SMEM row: 40 halves, 80 B pitch */

// ---------------- static device scratch (no runtime alloc allowed) ----------
// activations stored packed: uint32 per element = (hi fp16) | (lo fp16 << 16)
__device__ uint32_t g_xP [(size_t)NN * 128];
__device__ uint32_t g_hPA[(size_t)NN * 512];
__device__ uint32_t g_hPB[(size_t)NN * 512];
__device__ uint32_t g_aggP[(size_t)NN * 256];
__device__ int   g_deg[NN];
__device__ float g_deg_inv[NN];
__device__ int   g_row_off[NN];
__device__ int   g_fill[NN];
__device__ int   g_csr_src[EE];
__device__ int   g_counter;
__device__ __half g_Whi[NWTOT];
__device__ __half g_Wlo[NWTOT];

// ---------------- pack/unpack helpers ----------------------------------------
__device__ __forceinline__ void split2p(float x, float y, uint32_t& hi2, uint32_t& lo2) {
    asm("cvt.rn.f16x2.f32 %0, %1, %2;" : "=r"(hi2) : "f"(y), "f"(x));
    float hx, hy;
    asm("{\n\t.reg .b16 l, h;\n\tmov.b32 {l, h}, %2;\n\t"
        "cvt.f32.f16 %0, l;\n\tcvt.f32.f16 %1, h;\n\t}"
        : "=f"(hx), "=f"(hy) : "r"(hi2));
    float lx = x - hx, ly = y - hy;
    asm("cvt.rn.f16x2.f32 %0, %1, %2;" : "=r"(lo2) : "f"(ly), "f"(lx));
}

// two fp32 -> two packed (hi|lo) words
__device__ __forceinline__ void pack2(float x, float y, uint32_t& p0, uint32_t& p1) {
    uint32_t h2, l2;
    split2p(x, y, h2, l2);
    asm("prmt.b32 %0, %1, %2, 0x5410;" : "=r"(p0) : "r"(h2), "r"(l2));
    asm("prmt.b32 %0, %1, %2, 0x7632;" : "=r"(p1) : "r"(h2), "r"(l2));
}

// packed word -> fp32 value (hi + lo)
__device__ __forceinline__ float recon(uint32_t p) {
    float2 f = __half22float2(*reinterpret_cast<__half2*>(&p));
    return f.x + f.y;
}

// two packed words -> (hi0,hi1) and (lo0,lo1) fp16x2 words
__device__ __forceinline__ void deint(uint32_t p0, uint32_t p1, uint32_t& hi2, uint32_t& lo2) {
    asm("prmt.b32 %0, %1, %2, 0x5410;" : "=r"(hi2) : "r"(p0), "r"(p1));
    asm("prmt.b32 %0, %1, %2, 0x7632;" : "=r"(lo2) : "r"(p0), "r"(p1));
}

// ---------------- graph build ----------------------------------------------
__global__ void k_zero_deg() {
    int i = blockIdx.x * blockDim.x + threadIdx.x;
    if (i < NN) g_deg[i] = 0;
    if (i == 0) g_counter = 0;
}

__global__ void k_count_deg(const int* __restrict__ dst) {
    int e = blockIdx.x * blockDim.x + threadIdx.x;
    if (e < EE) atomicAdd(&g_deg[dst[e]], 1);
}

__global__ void k_offsets() {
    __shared__ int sh[256];
    __shared__ int base;
    int t = threadIdx.x;
    int i = blockIdx.x * 256 + t;
    int d = (i < NN) ? g_deg[i] : 0;
    sh[t] = d;
    __syncthreads();
    #pragma unroll
    for (int off = 1; off < 256; off <<= 1) {
        int v = (t >= off) ? sh[t - off] : 0;
        __syncthreads();
        sh[t] += v;
        __syncthreads();
    }
    int incl = sh[t];
    if (t == 255) base = atomicAdd(&g_counter, incl);
    __syncthreads();
    if (i < NN) {
        int o = base + incl - d;
        g_row_off[i] = o;
        g_fill[i]    = o;
        g_deg_inv[i] = 1.0f / fmaxf((float)d, 1.0f);
    }
}

__global__ void k_fill_csr(const int* __restrict__ src, const int* __restrict__ dst) {
    int e = blockIdx.x * blockDim.x + threadIdx.x;
    if (e < EE) {
        int p = atomicAdd(&g_fill[dst[e]], 1);
        g_csr_src[p] = src[e];
    }
}

// ---------------- weight + input pre-conversion -------------------------------
struct WP { const float* w[10]; };

__global__ void k_convW(WP p) {
    const int off[11] = {0, 16384, 32768, 40960, 49152, 57344,
                         65536, 98304, 131072, 262144, 393216};
    int i = blockIdx.x * 256 + threadIdx.x;
    if (i >= NWTOT) return;
    int s = 0;
    #pragma unroll
    for (int j = 1; j < 10; j++) if (i >= off[j]) s = j;
    float v = p.w[s][i - off[s]];
    __half h = __float2half_rn(v);
    g_Whi[i] = h;
    g_Wlo[i] = __float2half_rn(v - __half2float(h));
}

__global__ void k_convX(const float2* __restrict__ x2) {
    int i = blockIdx.x * 256 + threadIdx.x;       // NN*128/2 float2 pairs
    if (i >= NN * 64) return;
    float2 v = x2[i];
    uint32_t p0, p1;
    pack2(v.x, v.y, p0, p1);
    uint2 o; o.x = p0; o.y = p1;
    reinterpret_cast<uint2*>(g_xP)[i] = o;
}

// ---------------- aggregation (packed uint4 lanes, multi-node blocks) -------
__global__ void k_aggregate4(const uint4* __restrict__ h4, uint4* __restrict__ agg4,
                             int din4) {
    int n = blockIdx.x * blockDim.y + threadIdx.y;
    if (n >= NN) return;
    int k = threadIdx.x;               // 0..din4-1, 4 packed elements each
    int s = g_row_off[n];
    int e1 = s + g_deg[n];
    float4 acc = make_float4(0.f, 0.f, 0.f, 0.f);
    int e = s;
    for (; e + 3 < e1; e += 4) {
        int s0 = g_csr_src[e + 0];
        int s1 = g_csr_src[e + 1];
        int s2 = g_csr_src[e + 2];
        int s3 = g_csr_src[e + 3];
        uint4 v0 = h4[(size_t)s0 * din4 + k];
        uint4 v1 = h4[(size_t)s1 * din4 + k];
        uint4 v2 = h4[(size_t)s2 * din4 + k];
        uint4 v3 = h4[(size_t)s3 * din4 + k];
        acc.x += (recon(v0.x) + recon(v1.x)) + (recon(v2.x) + recon(v3.x));
        acc.y += (recon(v0.y) + recon(v1.y)) + (recon(v2.y) + recon(v3.y));
        acc.z += (recon(v0.z) + recon(v1.z)) + (recon(v2.z) + recon(v3.z));
        acc.w += (recon(v0.w) + recon(v1.w)) + (recon(v2.w) + recon(v3.w));
    }
    for (; e < e1; e++) {
        uint4 v = h4[(size_t)g_csr_src[e] * din4 + k];
        acc.x += recon(v.x); acc.y += recon(v.y);
        acc.z += recon(v.z); acc.w += recon(v.w);
    }
    float di = g_deg_inv[n];
    uint4 o;
    pack2(acc.x * di, acc.y * di, o.x, o.y);
    pack2(acc.z * di, acc.w * di, o.z, o.w);
    agg4[(size_t)n * din4 + k] = o;
}

// ---------------- fp16 (3x hi/lo split) mma.sync SAGE gemm -------------------
__device__ __forceinline__ void mma_f16(float* c, const uint32_t* a, const uint32_t* b) {
    asm volatile(
        "mma.sync.aligned.m16n8k16.row.col.f32.f16.f16.f32 "
        "{%0,%1,%2,%3}, {%4,%5,%6,%7}, {%8,%9}, {%0,%1,%2,%3};"
        : "+f"(c[0]), "+f"(c[1]), "+f"(c[2]), "+f"(c[3])
        : "r"(a[0]), "r"(a[1]), "r"(a[2]), "r"(a[3]), "r"(b[0]), "r"(b[1]));
}

__device__ __forceinline__ void ldm_x4(uint32_t* r, uint32_t addr) {
    asm volatile("ldmatrix.sync.aligned.m8n8.x4.shared.b16 {%0,%1,%2,%3}, [%4];"
                 : "=r"(r[0]), "=r"(r[1]), "=r"(r[2]), "=r"(r[3]) : "r"(addr));
}
__device__ __forceinline__ void ldm_x2(uint32_t* r, uint32_t addr) {
    asm volatile("ldmatrix.sync.aligned.m8n8.x2.shared.b16 {%0,%1}, [%2];"
                 : "=r"(r[0]), "=r"(r[1]) : "r"(addr));
}

template<int BN>
__global__ __launch_bounds__(256)
void k_gemm_f16(const uint32_t* __restrict__ A0, const uint32_t* __restrict__ A1,
                const __half* __restrict__ WhiL, const __half* __restrict__ WloL,
                const __half* __restrict__ WhiR, const __half* __restrict__ WloR,
                const float* __restrict__ bias, uint32_t* __restrict__ C,
                int din, int dout)
{
    constexpr int WN = BN / 4;
    constexpr int NT = WN / 8;
    constexpr int A_IT = 4;                   // uint4 (4 packed elems) / thread
    constexpr int B_IT = BN / 64;             // uint4 (8 halves) loads

    __shared__ uint32_t AsH[BM * P32], AsL[BM * P32];
    __shared__ uint32_t BsH[BN * P32], BsL[BN * P32];

    int tid = threadIdx.x;
    int wid = tid >> 5, lane = tid & 31;
    int wm = wid >> 2, wn = wid & 3;
    int lr = lane >> 2, q = lane & 3;
    int rowBase = blockIdx.x * BM;
    int colBase = blockIdx.y * BN;

    int aRow = (lane & 7) + 8 * ((lane >> 3) & 1);
    int aCol = 16 * ((lane >> 4) & 1);
    int bRow = lane & 7;
    int bCol = 16 * ((lane >> 3) & 1);
    uint32_t aBaseH = (uint32_t)__cvta_generic_to_shared(AsH) + (wm * 64 + aRow) * 80 + aCol;
    uint32_t aBaseL = (uint32_t)__cvta_generic_to_shared(AsL) + (wm * 64 + aRow) * 80 + aCol;
    uint32_t bBaseH = (uint32_t)__cvta_generic_to_shared(BsH) + (wn * WN + bRow) * 80 + bCol;
    uint32_t bBaseL = (uint32_t)__cvta_generic_to_shared(BsL) + (wn * WN + bRow) * 80 + bCol;

    float acc[4][NT][4];
    #pragma unroll
    for (int i = 0; i < 4; i++)
        #pragma unroll
        for (int j = 0; j < NT; j++)
            #pragma unroll
            for (int p = 0; p < 4; p++) acc[i][j][p] = 0.0f;

    const int K = 2 * din;
    const int nCh = K >> 5;

    uint4 pa[A_IT], pbh[B_IT], pbl[B_IT];

    auto loadChunk = [&](int ch) {
        int k0 = ch << 5;
        const uint32_t* Ag;
        const __half *Bh, *Bl;
        int kk;
        if (k0 < din) { Ag = A0; Bh = WhiL; Bl = WloL; kk = k0; }
        else          { Ag = A1; Bh = WhiR; Bl = WloR; kk = k0 - din; }
        #pragma unroll
        for (int it = 0; it < A_IT; it++) {
            int i = tid + it * 256;
            int r = i >> 3, c4 = (i & 7) << 2;
            int gr = rowBase + r;
            pa[it] = (gr < NN) ? *reinterpret_cast<const uint4*>(&Ag[(size_t)gr * din + kk + c4])
                               : make_uint4(0, 0, 0, 0);
        }
        #pragma unroll
        for (int it = 0; it < B_IT; it++) {
            int i = tid + it * 256;
            int r = i >> 2, c8 = (i & 3) << 3;
            size_t goff = (size_t)(colBase + r) * din + kk + c8;
            pbh[it] = *reinterpret_cast<const uint4*>(&Bh[goff]);
            pbl[it] = *reinterpret_cast<const uint4*>(&Bl[goff]);
        }
    };

    loadChunk(0);

    for (int ch = 0; ch < nCh; ch++) {
        // stage A: de-interleave packed pairs (4 PRMT per uint4)
        #pragma unroll
        for (int it = 0; it < A_IT; it++) {
            int i = tid + it * 256;
            int r = i >> 3, w = (i & 7) << 1;
            uint32_t h01, l01, h23, l23;
            deint(pa[it].x, pa[it].y, h01, l01);
            deint(pa[it].z, pa[it].w, h23, l23);
            AsH[r * P32 + w] = h01; AsH[r * P32 + w + 1] = h23;
            AsL[r * P32 + w] = l01; AsL[r * P32 + w + 1] = l23;
        }
        // stage B: pure copy of pre-converted weights
        #pragma unroll
        for (int it = 0; it < B_IT; it++) {
            int i = tid + it * 256;
            int r = i >> 2, w4 = (i & 3) << 2;
            *reinterpret_cast<uint4*>(&BsH[r * P32 + w4]) = pbh[it];
            *reinterpret_cast<uint4*>(&BsL[r * P32 + w4]) = pbl[it];
        }
        __syncthreads();

        if (ch + 1 < nCh) loadChunk(ch + 1);   // GMEM latency overlaps MMA

        #pragma unroll
        for (int ks = 0; ks < 2; ks++) {
            uint32_t kb = (uint32_t)(ks * 32);
            uint32_t ah[4][4], al[4][4], bh[NT][2], bl[NT][2];
            #pragma unroll
            for (int mt = 0; mt < 4; mt++) {
                uint32_t moff = (uint32_t)(mt * 16 * 80) + kb;
                ldm_x4(ah[mt], aBaseH + moff);
                ldm_x4(al[mt], aBaseL + moff);
            }
            #pragma unroll
            for (int nt = 0; nt < NT; nt++) {
                uint32_t noff = (uint32_t)(nt * 8 * 80) + kb;
                ldm_x2(bh[nt], bBaseH + noff);
                ldm_x2(bl[nt], bBaseL + noff);
            }
            #pragma unroll
            for (int mt = 0; mt < 4; mt++)
                #pragma unroll
                for (int nt = 0; nt < NT; nt++)
                    mma_f16(acc[mt][nt], ah[mt], bh[nt]);
            #pragma unroll
            for (int mt = 0; mt < 4; mt++)
                #pragma unroll
                for (int nt = 0; nt < NT; nt++)
                    mma_f16(acc[mt][nt], al[mt], bh[nt]);
            #pragma unroll
            for (int mt = 0; mt < 4; mt++)
                #pragma unroll
                for (int nt = 0; nt < NT; nt++)
                    mma_f16(acc[mt][nt], ah[mt], bl[nt]);
        }
        __syncthreads();
    }

    // epilogue: bias + relu + pack to (hi|lo) words
    #pragma unroll
    for (int mt = 0; mt < 4; mt++) {
        int r0 = rowBase + wm * 64 + mt * 16 + lr;
        int r1 = r0 + 8;
        #pragma unroll
        for (int nt = 0; nt < NT; nt++) {
            int c = colBase + wn * WN + nt * 8 + q * 2;
            float b0 = bias[c], b1 = bias[c + 1];
            if (r0 < NN) {
                float v0 = fmaxf(acc[mt][nt][0] + b0, 0.f);
                float v1 = fmaxf(acc[mt][nt][1] + b1, 0.f);
                uint2 o;
                pack2(v0, v1, o.x, o.y);
                *reinterpret_cast<uint2*>(&C[(size_t)r0 * dout + c]) = o;
            }
            if (r1 < NN) {
                float v0 = fmaxf(acc[mt][nt][2] + b0, 0.f);
                float v1 = fmaxf(acc[mt][nt][3] + b1, 0.f);
                uint2 o;
                pack2(v0, v1, o.x, o.y);
                *reinterpret_cast<uint2*>(&C[(size_t)r1 * dout + c]) = o;
            }
        }
    }
}

// ---------------- head: logits = h @ Wout^T + bout; softmax -----------------
__global__ void k_head(const uint4* __restrict__ h4, const float4* __restrict__ Wout4,
                       const float* __restrict__ bout, float* __restrict__ out) {
    int gwarp = (blockIdx.x * blockDim.x + threadIdx.x) >> 5;
    int lane  = threadIdx.x & 31;
    if (gwarp >= NN) return;
    const uint4* hr = h4 + (size_t)gwarp * 128;   // 512 packed words = 128 uint4
    float s[4] = {0.f, 0.f, 0.f, 0.f};
    #pragma unroll
    for (int it = 0; it < 4; it++) {
        int i = lane + it * 32;
        uint4 pv = hr[i];
        float4 hv = make_float4(recon(pv.x), recon(pv.y), recon(pv.z), recon(pv.w));
        #pragma unroll
        for (int c = 0; c < 4; c++) {
            float4 wv = Wout4[c * 128 + i];
            s[c] += hv.x * wv.x + hv.y * wv.y + hv.z * wv.z + hv.w * wv.w;
        }
    }
    #pragma unroll
    for (int off = 16; off > 0; off >>= 1)
        #pragma unroll
        for (int c = 0; c < 4; c++)
            s[c] += __shfl_xor_sync(0xFFFFFFFF, s[c], off);
    if (lane == 0) {
        float l[4];
        float m = -1e30f;
        #pragma unroll
        for (int c = 0; c < 4; c++) { l[c] = s[c] + bout[c]; m = fmaxf(m, l[c]); }
        float den = 0.f;
        #pragma unroll
        for (int c = 0; c < 4; c++) { l[c] = __expf(l[c] - m); den += l[c]; }
        float inv = 1.0f / den;
        #pragma unroll
        for (int c = 0; c < 4; c++) out[(size_t)gwarp * 4 + c] = l[c] * inv;
    }
}

// ---------------- driver -----------------------------------------------------
extern "C" void kernel_launch(void* const* d_in, const int* in_sizes, int n_in,
                              void* d_out, int out_size)
{
    const float* x    = (const float*)d_in[0];
    const float* Wl[5] = {(const float*)d_in[1],  (const float*)d_in[4],
                          (const float*)d_in[7],  (const float*)d_in[10],
                          (const float*)d_in[13]};
    const float* bl[5] = {(const float*)d_in[2],  (const float*)d_in[5],
                          (const float*)d_in[8],  (const float*)d_in[11],
                          (const float*)d_in[14]};
    const float* Wr[5] = {(const float*)d_in[3],  (const float*)d_in[6],
                          (const float*)d_in[9],  (const float*)d_in[12],
                          (const float*)d_in[15]};
    const float* Wout = (const float*)d_in[16];
    const float* bout = (const float*)d_in[17];
    const int*   ei   = (const int*)d_in[18];
    const int* src = ei;
    const int* dst = ei + EE;

    uint32_t *xP, *hPA, *hPB, *aggP;
    __half *whi, *wlo;
    cudaGetSymbolAddress((void**)&xP,  g_xP);
    cudaGetSymbolAddress((void**)&hPA, g_hPA);
    cudaGetSymbolAddress((void**)&hPB, g_hPB);
    cudaGetSymbolAddress((void**)&aggP, g_aggP);
    cudaGetSymbolAddress((void**)&whi, g_Whi);
    cudaGetSymbolAddress((void**)&wlo, g_Wlo);

    // 0. convert weights + input once per call
    WP wp;
    for (int i = 0; i < 5; i++) { wp.w[2 * i] = Wl[i]; wp.w[2 * i + 1] = Wr[i]; }
    k_convW<<<(NWTOT + 255) / 256, 256>>>(wp);
    k_convX<<<(NN * 64 + 255) / 256, 256>>>((const float2*)x);

    // 1. build CSR by dst
    k_zero_deg<<<(NN + 255) / 256, 256>>>();
    k_count_deg<<<(EE + 255) / 256, 256>>>(dst);
    k_offsets<<<(NN + 255) / 256, 256>>>();
    k_fill_csr<<<(EE + 255) / 256, 256>>>(src, dst);

    // 2. layers
    const int dins[5]  = {128, 128, 64, 128, 256};
    const int douts[5] = {128,  64, 128, 256, 512};
    const int woff[10] = {0, 16384, 32768, 40960, 49152, 57344,
                          65536, 98304, 131072, 262144};
    const uint32_t* hcur = xP;
    uint32_t* bufs[2] = {hPA, hPB};
    for (int i = 0; i < 5; i++) {
        int din = dins[i], dout = douts[i];
        int din4 = din / 4;
        int npb = 128 / din4;
        dim3 ablk(din4, npb);
        k_aggregate4<<<(NN + npb - 1) / npb, ablk>>>(
            (const uint4*)hcur, (uint4*)aggP, din4);
        uint32_t* hnext = bufs[i & 1];
        const __half* whl = whi + woff[2 * i];
        const __half* wll = wlo + woff[2 * i];
        const __half* whr = whi + woff[2 * i + 1];
        const __half* wlr = wlo + woff[2 * i + 1];
        if (dout >= 128) {
            dim3 grid((NN + BM - 1) / BM, dout / 128);
            k_gemm_f16<128><<<grid, 256>>>(aggP, hcur, whl, wll, whr, wlr,
                                           bl[i], hnext, din, dout);
        } else {
            dim3 grid((NN + BM - 1) / BM, 1);
            k_gemm_f16<64><<<grid, 256>>>(aggP, hcur, whl, wll, whr, wlr,
                                          bl[i], hnext, din, dout);
        }
        hcur = hnext;
    }

    // 3. head + softmax
    k_head<<<(NN * 32 + 255) / 256, 256>>>((const uint4*)hcur, (const float4*)Wout,
                                           bout, (float*)d_out);
}